// round 11
// baseline (speedup 1.0000x reference)
#include <cuda_runtime.h>
#include <cuda_bf16.h>
#include <cstdint>

#define W_DIM   21504
#define NSEG    64
#define NELEM   8192
#define TILE_R  64
#define MAX_TILES 192
#define TPB     256
#define SEG_U4  5376        // uint4 fragments per segment
#define NITEMS  5376
#define NBLOCKS 444         // 148 SMs x 3 CTAs

// ---------------- device globals ----------------
__device__ int  d_starts[NSEG + 1];
__device__ int2 d_tiles[MAX_TILES];
__device__ int  d_ntiles;
__device__ int  d_work;
__device__ __align__(16) uint4 d_wb[NSEG * SEG_U4];  // mma-fragment-ordered weights

// ---------------- wrappers ----------------
__device__ __forceinline__ void ldsm4(uint32_t* r, unsigned addr) {
    asm volatile("ldmatrix.sync.aligned.m8n8.x4.shared.b16 {%0,%1,%2,%3}, [%4];"
                 : "=r"(r[0]), "=r"(r[1]), "=r"(r[2]), "=r"(r[3]) : "r"(addr));
}
__device__ __forceinline__ void mma_bf16(float* c, const uint32_t* a,
                                         uint32_t b0, uint32_t b1) {
    asm volatile("mma.sync.aligned.m16n8k16.row.col.f32.bf16.bf16.f32 "
                 "{%0,%1,%2,%3}, {%4,%5,%6,%7}, {%8,%9}, {%0,%1,%2,%3};"
                 : "+f"(c[0]), "+f"(c[1]), "+f"(c[2]), "+f"(c[3])
                 : "r"(a[0]), "r"(a[1]), "r"(a[2]), "r"(a[3]), "r"(b0), "r"(b1));
}
__device__ __forceinline__ uint32_t bfpair(float a, float b) {
    __nv_bfloat162 p = __floats2bfloat162_rn(a, b);   // .x = a = low half
    return *reinterpret_cast<uint32_t*>(&p);
}
__device__ __forceinline__ void sts_v2(unsigned addr, uint32_t a, uint32_t b) {
    asm volatile("st.shared.v2.b32 [%0], {%1,%2};" :: "r"(addr), "r"(a), "r"(b));
}

// ---------------- prekernel: wconv (smem-staged) + scan + counter reset -----
__global__ void pre_kernel(const int* __restrict__ counts,
                           const float* __restrict__ w) {
    if (blockIdx.x == NSEG) {
        __shared__ int wsum[2], wtsum[2];
        const int t = threadIdx.x;
        if (t == 0) d_work = 0;
        int c = 0, nt = 0, sc = 0, st = 0;
        if (t < 64) {
            c  = counts[t];
            nt = (c + TILE_R - 1) >> 6;
            sc = c; st = nt;
            #pragma unroll
            for (int d = 1; d < 32; d <<= 1) {
                int a = __shfl_up_sync(0xffffffffu, sc, d);
                int b = __shfl_up_sync(0xffffffffu, st, d);
                if ((t & 31) >= d) { sc += a; st += b; }
            }
            if ((t & 31) == 31) { wsum[t >> 5] = sc; wtsum[t >> 5] = st; }
        }
        __syncthreads();
        if (t < 64) {
            if (t >= 32) { sc += wsum[0]; st += wtsum[0]; }
            const int startc = sc - c;
            const int startt = st - nt;
            d_starts[t] = startc;
            if (t == 63) { d_starts[NSEG] = sc; d_ntiles = st; }
            for (int k = 0; k < nt; k++)
                d_tiles[startt + k] = make_int2(startc + TILE_R * k, t);
        }
        return;
    }
    // ---- weight convert: coalesced smem stage, then fragment assembly ----
    extern __shared__ float ws[];          // 21504 floats = 86016 B
    const int g = blockIdx.x;
    const float4* src4 = reinterpret_cast<const float4*>(w + (size_t)g * W_DIM);
    #pragma unroll 4
    for (int j = threadIdx.x; j < W_DIM / 4; j += 256)
        reinterpret_cast<float4*>(ws)[j] = src4[j];
    __syncthreads();

    uint4* dst = d_wb + (size_t)g * SEG_U4;
    for (int it = threadIdx.x; it < NITEMS; it += 256) {
        int MUL, KS, WOFF, base; float coeff; int rem;
        if (it < 4096)      { MUL=128; KS=8; WOFF=0;     base=0;    coeff=0.011048543456039806f; rem=it; }
        else if (it < 5120) { MUL=64;  KS=4; WOFF=16384; base=4096; coeff=0.015625f;             rem=it-4096; }
        else                { MUL=32;  KS=2; WOFF=20480; base=5120; coeff=0.022097086912079613f; rem=it-5120; }
        const int lane = rem & 31;
        const int fr   = rem >> 5;
        const int ks   = fr % KS;
        const int nbl  = fr / KS;
        const int o    = nbl * 8 + (lane >> 2);
        const int mb   = ks * 16 + (lane & 3) * 2;
        uint32_t hi[2], lo[2];
        #pragma unroll
        for (int r = 0; r < 2; r++) {
            float v0 = coeff * ws[WOFF + (mb + r * 8)     * MUL + o];
            float v1 = coeff * ws[WOFF + (mb + r * 8 + 1) * MUL + o];
            __nv_bfloat16 h0 = __float2bfloat16(v0);
            __nv_bfloat16 h1 = __float2bfloat16(v1);
            hi[r] = bfpair(v0, v1);
            lo[r] = bfpair(v0 - __bfloat162float(h0), v1 - __bfloat162float(h1));
        }
        dst[base + fr * 32 + lane] = make_uint4(hi[0], hi[1], lo[0], lo[1]);
    }
}

// ---------------- per-tile compute: A in smem, B fragments from global ------
template <int MUL, int DIM, int IOFF4>
__device__ __forceinline__ void run_irrep_mma(const float* __restrict__ x,
                                              float* __restrict__ y,
                                              int tile, __nv_bfloat16* As) {
    constexpr int K   = MUL;
    constexpr int CH  = MUL * DIM;
    constexpr int LD  = 2 * K + 8;
    constexpr int WM  = DIM;
    constexpr int NBW = MUL / 16;
    constexpr int KS  = MUL / 16;

    const int2 tt  = d_tiles[tile];
    const int row0 = tt.x;
    const int g    = tt.y;
    int nrows = d_starts[g + 1] - row0;
    if (nrows > TILE_R) nrows = TILE_R;

    const unsigned sbase = (unsigned)__cvta_generic_to_shared(As);

    // ---- stage A (hi|lo planes) ----
    const float* xt = x + (size_t)row0 * CH;
    constexpr int IPR = MUL / 4;
    for (int e = threadIdx.x; e < 64 * IPR; e += TPB) {
        int r  = e / IPR;
        int m0 = (e - r * IPR) * 4;
        const float* src = xt + (size_t)r * CH + m0 * DIM;
        float f[4 * DIM];
        if (r < nrows) {
            #pragma unroll
            for (int d = 0; d < DIM; d++) {
                float4 v = *reinterpret_cast<const float4*>(src + 4 * d);
                f[4*d] = v.x; f[4*d+1] = v.y; f[4*d+2] = v.z; f[4*d+3] = v.w;
            }
        } else {
            #pragma unroll
            for (int j = 0; j < 4 * DIM; j++) f[j] = 0.f;
        }
        #pragma unroll
        for (int i = 0; i < DIM; i++) {
            float a = f[i], b = f[DIM + i], c = f[2*DIM + i], d2 = f[3*DIM + i];
            float ha = __bfloat162float(__float2bfloat16(a));
            float hb = __bfloat162float(__float2bfloat16(b));
            float hc = __bfloat162float(__float2bfloat16(c));
            float hd = __bfloat162float(__float2bfloat16(d2));
            unsigned ab = sbase + (unsigned)((r * DIM + i) * LD + m0) * 2u;
            sts_v2(ab,          bfpair(a, b),           bfpair(c, d2));
            sts_v2(ab + 2u * K, bfpair(a - ha, b - hb), bfpair(c - hc, d2 - hd));
        }
    }
    __syncthreads();

    const int l  = threadIdx.x & 31;
    const int wp = threadIdx.x >> 5;
    const int wm = wp & 3, nh = wp >> 2;

    const unsigned a_lane = ((l & 15) * LD + ((l >> 4) << 3)) * 2u;
    const uint4* wfrag = d_wb + (size_t)g * SEG_U4 + IOFF4
                       + (size_t)(nh * NBW) * KS * 32 + l;

    float acc[WM][NBW][4];
    #pragma unroll
    for (int mt = 0; mt < WM; mt++)
        #pragma unroll
        for (int nb = 0; nb < NBW; nb++)
            #pragma unroll
            for (int q = 0; q < 4; q++) acc[mt][nb][q] = 0.f;

    for (int ks = 0; ks < KS; ks++) {
        uint32_t af[WM][2][4];
        #pragma unroll
        for (int mt = 0; mt < WM; mt++) {
            unsigned ab = sbase + (unsigned)(((wm * WM + mt) * 16) * LD) * 2u
                        + (unsigned)ks * 32u + a_lane;
            ldsm4(af[mt][0], ab);           // x hi
            ldsm4(af[mt][1], ab + K * 2u);  // x lo
        }
        #pragma unroll
        for (int nb = 0; nb < NBW; nb++) {
            const uint4 bf = wfrag[(nb * KS + ks) * 32];
            #pragma unroll
            for (int mt = 0; mt < WM; mt++) {
                mma_bf16(acc[mt][nb], af[mt][0], bf.x, bf.y);  // xh*wh
                mma_bf16(acc[mt][nb], af[mt][0], bf.z, bf.w);  // xh*wl
                mma_bf16(acc[mt][nb], af[mt][1], bf.x, bf.y);  // xl*wh
            }
        }
    }

    // ---- epilogue: C[(r,i)][o] -> y[r][o*DIM + i] ----
    float* yt = y + (size_t)row0 * CH;
    #pragma unroll
    for (int mt = 0; mt < WM; mt++) {
        const int mrow0 = (wm * WM + mt) * 16 + (l >> 2);
        #pragma unroll
        for (int nb = 0; nb < NBW; nb++) {
            const int n0 = nh * (MUL / 2) + nb * 8 + (l & 3) * 2;
            #pragma unroll
            for (int rr = 0; rr < 2; rr++) {
                const int mrow = mrow0 + rr * 8;
                const int r = mrow / DIM;
                const int i = mrow - r * DIM;
                if (r < nrows) {
                    const float v0 = acc[mt][nb][rr * 2 + 0];
                    const float v1 = acc[mt][nb][rr * 2 + 1];
                    if (DIM == 1) {
                        *reinterpret_cast<float2*>(&yt[(size_t)r * CH + n0]) =
                            make_float2(v0, v1);
                    } else {
                        yt[(size_t)r * CH + n0 * DIM + i]       = v0;
                        yt[(size_t)r * CH + (n0 + 1) * DIM + i] = v1;
                    }
                }
            }
        }
    }
}

// smem (A only): irrep1 max: 192*136*2 = 52224 B
#define SMEM_BYTES 52224
#define WSMEM_BYTES 86016

__global__ __launch_bounds__(TPB, 3)
void lin_main(const float* __restrict__ x0, const float* __restrict__ x1,
              const float* __restrict__ x2, float* __restrict__ out) {
    extern __shared__ __nv_bfloat16 smem_bf[];
    __shared__ int s_item;
    const int nitems = 3 * d_ntiles;
    for (;;) {
        if (threadIdx.x == 0) s_item = atomicAdd(&d_work, 1);
        __syncthreads();
        const int item = s_item;
        if (item >= nitems) return;
        const int irr  = item % 3;
        const int tile = item / 3;
        if (irr == 0) {
            run_irrep_mma<128, 1, 0>(x0, out, tile, smem_bf);
        } else if (irr == 1) {
            run_irrep_mma<64, 3, 4096>(x1, out + (size_t)NELEM * 128, tile, smem_bf);
        } else {
            run_irrep_mma<32, 5, 5120>(x2, out + (size_t)NELEM * (128 + 192), tile, smem_bf);
        }
        __syncthreads();   // protect smem + s_item reuse
    }
}

extern "C" void kernel_launch(void* const* d_in, const int* in_sizes, int n_in,
                              void* d_out, int out_size) {
    const float* x0     = (const float*)d_in[0];
    const float* x1     = (const float*)d_in[1];
    const float* x2     = (const float*)d_in[2];
    const float* w      = (const float*)d_in[3];
    const int*   counts = (const int*)d_in[4];
    float*       out    = (float*)d_out;

    cudaFuncSetAttribute(pre_kernel, cudaFuncAttributeMaxDynamicSharedMemorySize,
                         WSMEM_BYTES);
    cudaFuncSetAttribute(lin_main, cudaFuncAttributeMaxDynamicSharedMemorySize,
                         SMEM_BYTES);
    pre_kernel<<<NSEG + 1, 256, WSMEM_BYTES>>>(counts, w);
    lin_main<<<NBLOCKS, TPB, SMEM_BYTES>>>(x0, x1, x2, out);
}

// round 14
// speedup vs baseline: 1.7380x; 1.7380x over previous
#include <cuda_runtime.h>
#include <cuda_fp16.h>
#include <cstdint>

#define W_DIM   21504
#define NSEG    64
#define NELEM   8192
#define TILE_R  32
#define MAX_TILES 320
#define TPB     256
#define SEG_U2  5376        // uint2 fp16 fragments per segment (43008 B)

// ---------------- device globals ----------------
__device__ int  d_starts[NSEG + 1];
__device__ int2 d_tiles[MAX_TILES];
__device__ int  d_ntiles;
__device__ __align__(16) uint2 d_wf[NSEG * SEG_U2];  // mma-fragment-ordered fp16 weights

// ---------------- wrappers ----------------
__device__ __forceinline__ void ldsm4(uint32_t* r, unsigned addr) {
    asm volatile("ldmatrix.sync.aligned.m8n8.x4.shared.b16 {%0,%1,%2,%3}, [%4];"
                 : "=r"(r[0]), "=r"(r[1]), "=r"(r[2]), "=r"(r[3]) : "r"(addr));
}
__device__ __forceinline__ void mma_f16(float* c, const uint32_t* a,
                                        uint32_t b0, uint32_t b1) {
    asm volatile("mma.sync.aligned.m16n8k16.row.col.f32.f16.f16.f32 "
                 "{%0,%1,%2,%3}, {%4,%5,%6,%7}, {%8,%9}, {%0,%1,%2,%3};"
                 : "+f"(c[0]), "+f"(c[1]), "+f"(c[2]), "+f"(c[3])
                 : "r"(a[0]), "r"(a[1]), "r"(a[2]), "r"(a[3]), "r"(b0), "r"(b1));
}
__device__ __forceinline__ uint32_t packh(float a, float b) {
    __half2 h = __floats2half2_rn(a, b);    // .x = a = low half (even k)
    return *reinterpret_cast<uint32_t*>(&h);
}
__device__ __forceinline__ void sts128(unsigned a, uint32_t x, uint32_t y,
                                       uint32_t z, uint32_t w) {
    asm volatile("st.shared.v4.b32 [%0], {%1,%2,%3,%4};"
                 :: "r"(a), "r"(x), "r"(y), "r"(z), "r"(w));
}
__device__ __forceinline__ unsigned smem_u32(const void* p) {
    unsigned a;
    asm("{ .reg .u64 t; cvta.to.shared.u64 t, %1; cvt.u32.u64 %0, t; }"
        : "=r"(a) : "l"(p));
    return a;
}

// ---------------- prekernel: fp16 fragment build (smem-staged) + scan -------
__global__ void pre_kernel(const int* __restrict__ counts,
                           const float* __restrict__ w) {
    if (blockIdx.x == NSEG) {
        __shared__ int wsum[2], wtsum[2];
        const int t = threadIdx.x;
        int c = 0, nt = 0, sc = 0, st = 0;
        if (t < 64) {
            c  = counts[t];
            nt = (c + TILE_R - 1) >> 5;
            sc = c; st = nt;
            #pragma unroll
            for (int d = 1; d < 32; d <<= 1) {
                int a = __shfl_up_sync(0xffffffffu, sc, d);
                int b = __shfl_up_sync(0xffffffffu, st, d);
                if ((t & 31) >= d) { sc += a; st += b; }
            }
            if ((t & 31) == 31) { wsum[t >> 5] = sc; wtsum[t >> 5] = st; }
        }
        __syncthreads();
        if (t < 64) {
            if (t >= 32) { sc += wsum[0]; st += wtsum[0]; }
            const int startc = sc - c;
            const int startt = st - nt;
            d_starts[t] = startc;
            if (t == 63) { d_starts[NSEG] = sc; d_ntiles = st; }
            for (int k = 0; k < nt; k++)
                d_tiles[startt + k] = make_int2(startc + TILE_R * k, t);
        }
        return;
    }
    extern __shared__ float ws[];          // 21504 floats = 86016 B
    const int g = blockIdx.x;
    const float4* src4 = reinterpret_cast<const float4*>(w + (size_t)g * W_DIM);
    #pragma unroll 4
    for (int j = threadIdx.x; j < W_DIM / 4; j += 256)
        reinterpret_cast<float4*>(ws)[j] = src4[j];
    __syncthreads();

    // frag (irr, nbl, ks, lane): uint2 {b0, b1}
    //   b0 = fp16x2 w(m0, o), w(m0+1, o);  b1 = w(m0+8, o), w(m0+9, o)
    //   m0 = ks*16 + (lane&3)*2 ; o = nbl*8 + (lane>>2)
    uint2* dst = d_wf + (size_t)g * SEG_U2;
    for (int it = threadIdx.x; it < SEG_U2; it += 256) {
        int MUL, KS, WOFF, base; float coeff; int rem;
        if (it < 4096)      { MUL=128; KS=8; WOFF=0;     base=0;    coeff=0.011048543456039806f; rem=it; }
        else if (it < 5120) { MUL=64;  KS=4; WOFF=16384; base=4096; coeff=0.015625f;             rem=it-4096; }
        else                { MUL=32;  KS=2; WOFF=20480; base=5120; coeff=0.022097086912079613f; rem=it-5120; }
        const int lane = rem & 31;
        const int fr   = rem >> 5;
        const int ks   = fr % KS;
        const int nbl  = fr / KS;
        const int o    = nbl * 8 + (lane >> 2);
        const int m0   = ks * 16 + (lane & 3) * 2;
        const float* wb = ws + WOFF + o;
        uint32_t b0 = packh(coeff * wb[(m0)     * MUL], coeff * wb[(m0 + 1) * MUL]);
        uint32_t b1 = packh(coeff * wb[(m0 + 8) * MUL], coeff * wb[(m0 + 9) * MUL]);
        dst[base + fr * 32 + lane] = make_uint2(b0, b1);
    }
}

// ---------------- main: fp16 2-term mma per 32-row tile ----------------
// GEMM per tile: M' = 32*DIM, N = K = MUL.  A[(r*DIM+i)][m] = x[r][m][i]
// split hi/lo fp16; B = single fp16 (coeff folded), fragments from global.
template <int MUL, int DIM, int IOFF2>
__device__ __forceinline__ void run_irrep(const float* __restrict__ x,
                                          float* __restrict__ y,
                                          int tile, __half* As) {
    constexpr int K   = MUL;
    constexpr int CH  = MUL * DIM;
    constexpr int LD  = 2 * K + 8;         // fp16 elems per A row (hi|lo + pad)
    constexpr int WM  = DIM;               // m16 tiles per warp (2 M-groups)
    constexpr int NBW = MUL / 32;          // n8 blocks per warp (4 N-groups)
    constexpr int KS  = MUL / 16;

    const int2 tt  = d_tiles[tile];
    const int row0 = tt.x;
    const int g    = tt.y;
    int nrows = d_starts[g + 1] - row0;
    if (nrows > TILE_R) nrows = TILE_R;

    const unsigned sbase = smem_u32(As);
    const int tid = threadIdx.x;

    // ---- stage A: x -> fp16 hi/lo planes, row-major [rowp][k] ----
    const float* xt = x + (size_t)row0 * CH;
    constexpr int IPR = K / 8;
    for (int e = tid; e < TILE_R * IPR; e += TPB) {
        const int r  = e / IPR;
        const int m0 = (e - r * IPR) * 8;
        float f[8 * DIM];
        if (r < nrows) {
            const float4* s = reinterpret_cast<const float4*>(xt + (size_t)r * CH + m0 * DIM);
            #pragma unroll
            for (int q = 0; q < 2 * DIM; q++) {
                float4 v = s[q];
                f[4*q] = v.x; f[4*q+1] = v.y; f[4*q+2] = v.z; f[4*q+3] = v.w;
            }
        } else {
            #pragma unroll
            for (int q = 0; q < 8 * DIM; q++) f[q] = 0.f;
        }
        #pragma unroll
        for (int i = 0; i < DIM; i++) {
            uint32_t hi[4], lo[4];
            #pragma unroll
            for (int q = 0; q < 4; q++) {
                float a = f[(2*q)   * DIM + i];
                float b = f[(2*q+1) * DIM + i];
                __half ha = __float2half(a);
                __half hb = __float2half(b);
                hi[q] = packh(__half2float(ha), __half2float(hb));
                lo[q] = packh(a - __half2float(ha), b - __half2float(hb));
            }
            const unsigned ab = sbase + (unsigned)((r * DIM + i) * LD + m0) * 2u;
            sts128(ab,          hi[0], hi[1], hi[2], hi[3]);
            sts128(ab + 2u * K, lo[0], lo[1], lo[2], lo[3]);
        }
    }
    __syncthreads();

    const int l  = tid & 31;
    const int wp = tid >> 5;
    const int wm = wp & 1;                 // 2 groups along M'
    const int nh = wp >> 1;                // 4 groups along N

    const unsigned a_lane = ((l & 15) * LD + ((l >> 4) << 3)) * 2u;
    const uint2* wfrag = d_wf + (size_t)g * SEG_U2 + IOFF2
                       + (size_t)(nh * NBW) * KS * 32 + l;

    float acc[WM][NBW][4];
    #pragma unroll
    for (int mt = 0; mt < WM; mt++)
        #pragma unroll
        for (int nb = 0; nb < NBW; nb++)
            #pragma unroll
            for (int q = 0; q < 4; q++) acc[mt][nb][q] = 0.f;

    for (int ks = 0; ks < KS; ks++) {
        uint2 bf[NBW];
        #pragma unroll
        for (int nb = 0; nb < NBW; nb++)
            bf[nb] = __ldg(&wfrag[(nb * KS + ks) * 32]);
        #pragma unroll
        for (int mt = 0; mt < WM; mt++) {
            const unsigned ab = sbase
                + (unsigned)(((wm * DIM + mt) * 16) * LD) * 2u
                + (unsigned)ks * 32u + a_lane;
            uint32_t ah[4], al[4];
            ldsm4(ah, ab);                 // x hi plane
            ldsm4(al, ab + 2u * K);        // x lo plane
            #pragma unroll
            for (int nb = 0; nb < NBW; nb++) {
                mma_f16(acc[mt][nb], ah, bf[nb].x, bf[nb].y);
                mma_f16(acc[mt][nb], al, bf[nb].x, bf[nb].y);
            }
        }
    }

    // ---- epilogue: C[(r,i)][o] -> y[r][o*DIM + i] ----
    float* yt = y + (size_t)row0 * CH;
    #pragma unroll
    for (int mt = 0; mt < WM; mt++) {
        const int mrow0 = (wm * DIM + mt) * 16 + (l >> 2);
        #pragma unroll
        for (int nb = 0; nb < NBW; nb++) {
            const int n0 = nh * (MUL / 4) + nb * 8 + (l & 3) * 2;
            #pragma unroll
            for (int rr = 0; rr < 2; rr++) {
                const int mrow = mrow0 + rr * 8;
                const int r = mrow / DIM;
                const int i = mrow - r * DIM;
                if (r < nrows) {
                    const float v0 = acc[mt][nb][rr * 2 + 0];
                    const float v1 = acc[mt][nb][rr * 2 + 1];
                    if (DIM == 1) {
                        *reinterpret_cast<float2*>(&yt[(size_t)r * CH + n0]) =
                            make_float2(v0, v1);
                    } else {
                        yt[(size_t)r * CH + n0 * DIM + i]       = v0;
                        yt[(size_t)r * CH + (n0 + 1) * DIM + i] = v1;
                    }
                }
            }
        }
    }
}

// static smem: max over irreps of 32*DIM*LD fp16:
//   irrep0: 32*264=8448; irrep1: 96*136=13056 (max); irrep2: 160*72=11520
#define SMEM_HALFS 13056
#define WSMEM_BYTES 86016

__global__ __launch_bounds__(TPB, 4)
void lin_main(const float* __restrict__ x0, const float* __restrict__ x1,
              const float* __restrict__ x2, float* __restrict__ out) {
    __shared__ __align__(16) __half As[SMEM_HALFS];
    const int b    = blockIdx.x;
    const int irr  = b % 3;                // interleave heavy/light tiles
    const int tile = b / 3;
    if (tile >= d_ntiles) return;
    if (irr == 0) {
        run_irrep<128, 1, 0>(x0, out, tile, As);
    } else if (irr == 1) {
        run_irrep<64, 3, 4096>(x1, out + (size_t)NELEM * 128, tile, As);
    } else {
        run_irrep<32, 5, 5120>(x2, out + (size_t)NELEM * (128 + 192), tile, As);
    }
}

extern "C" void kernel_launch(void* const* d_in, const int* in_sizes, int n_in,
                              void* d_out, int out_size) {
    const float* x0     = (const float*)d_in[0];
    const float* x1     = (const float*)d_in[1];
    const float* x2     = (const float*)d_in[2];
    const float* w      = (const float*)d_in[3];
    const int*   counts = (const int*)d_in[4];
    float*       out    = (float*)d_out;

    cudaFuncSetAttribute(pre_kernel, cudaFuncAttributeMaxDynamicSharedMemorySize,
                         WSMEM_BYTES);
    pre_kernel<<<NSEG + 1, 256, WSMEM_BYTES>>>(counts, w);
    lin_main<<<3 * MAX_TILES, TPB>>>(x0, x1, x2, out);
}

// round 15
// speedup vs baseline: 1.7618x; 1.0137x over previous
#include <cuda_runtime.h>
#include <cuda_fp16.h>
#include <cstdint>

#define W_DIM   21504
#define NSEG    64
#define NELEM   8192
#define TILE_R  32
#define MAX_TILES 320
#define TPB     256
#define SEG_U2  5376        // uint2 fp16 fragments per segment
#define PRE_Q   1344        // items per pre-block (SEG_U2/4)

// ---------------- device globals ----------------
__device__ int  d_starts[NSEG + 1];
__device__ int2 d_tiles[MAX_TILES];
__device__ int  d_ntiles;
__device__ __align__(16) uint2 d_wf[NSEG * SEG_U2];  // mma-fragment-ordered fp16 weights

// ---------------- wrappers ----------------
__device__ __forceinline__ void ldsm4(uint32_t* r, unsigned addr) {
    asm volatile("ldmatrix.sync.aligned.m8n8.x4.shared.b16 {%0,%1,%2,%3}, [%4];"
                 : "=r"(r[0]), "=r"(r[1]), "=r"(r[2]), "=r"(r[3]) : "r"(addr));
}
__device__ __forceinline__ void mma_f16(float* c, const uint32_t* a,
                                        uint32_t b0, uint32_t b1) {
    asm volatile("mma.sync.aligned.m16n8k16.row.col.f32.f16.f16.f32 "
                 "{%0,%1,%2,%3}, {%4,%5,%6,%7}, {%8,%9}, {%0,%1,%2,%3};"
                 : "+f"(c[0]), "+f"(c[1]), "+f"(c[2]), "+f"(c[3])
                 : "r"(a[0]), "r"(a[1]), "r"(a[2]), "r"(a[3]), "r"(b0), "r"(b1));
}
__device__ __forceinline__ uint32_t packh(float a, float b) {
    __half2 h = __floats2half2_rn(a, b);    // .x = a = low half (even k)
    return *reinterpret_cast<uint32_t*>(&h);
}
__device__ __forceinline__ void sts128(unsigned a, uint32_t x, uint32_t y,
                                       uint32_t z, uint32_t w) {
    asm volatile("st.shared.v4.b32 [%0], {%1,%2,%3,%4};"
                 :: "r"(a), "r"(x), "r"(y), "r"(z), "r"(w));
}
__device__ __forceinline__ unsigned smem_u32(const void* p) {
    unsigned a;
    asm("{ .reg .u64 t; cvta.to.shared.u64 t, %1; cvt.u32.u64 %0, t; }"
        : "=r"(a) : "l"(p));
    return a;
}

// ---------------- prekernel: direct-gather fp16 fragments + scan ------------
__global__ void pre_kernel(const int* __restrict__ counts,
                           const float* __restrict__ w) {
    if (blockIdx.x == 4 * NSEG) {
        __shared__ int wsum[2], wtsum[2];
        const int t = threadIdx.x;
        int c = 0, nt = 0, sc = 0, st = 0;
        if (t < 64) {
            c  = counts[t];
            nt = (c + TILE_R - 1) >> 5;
            sc = c; st = nt;
            #pragma unroll
            for (int d = 1; d < 32; d <<= 1) {
                int a = __shfl_up_sync(0xffffffffu, sc, d);
                int b = __shfl_up_sync(0xffffffffu, st, d);
                if ((t & 31) >= d) { sc += a; st += b; }
            }
            if ((t & 31) == 31) { wsum[t >> 5] = sc; wtsum[t >> 5] = st; }
        }
        __syncthreads();
        if (t < 64) {
            if (t >= 32) { sc += wsum[0]; st += wtsum[0]; }
            const int startc = sc - c;
            const int startt = st - nt;
            d_starts[t] = startc;
            if (t == 63) { d_starts[NSEG] = sc; d_ntiles = st; }
            for (int k = 0; k < nt; k++)
                d_tiles[startt + k] = make_int2(startc + TILE_R * k, t);
        }
        return;
    }
    // Each w element feeds exactly one fragment -> direct gather, no staging.
    const int g = blockIdx.x >> 2;
    const int q = blockIdx.x & 3;
    const float* wg = w + (size_t)g * W_DIM;
    uint2* dst = d_wf + (size_t)g * SEG_U2;
    const int end = (q + 1) * PRE_Q;
    for (int it = q * PRE_Q + threadIdx.x; it < end; it += 256) {
        int MUL, KS, WOFF, base; float coeff; int rem;
        if (it < 4096)      { MUL=128; KS=8; WOFF=0;     base=0;    coeff=0.011048543456039806f; rem=it; }
        else if (it < 5120) { MUL=64;  KS=4; WOFF=16384; base=4096; coeff=0.015625f;             rem=it-4096; }
        else                { MUL=32;  KS=2; WOFF=20480; base=5120; coeff=0.022097086912079613f; rem=it-5120; }
        const int lane = rem & 31;
        const int fr   = rem >> 5;
        const int ks   = fr % KS;
        const int nbl  = fr / KS;
        const int o    = nbl * 8 + (lane >> 2);
        const int m0   = ks * 16 + (lane & 3) * 2;
        const float* wb = wg + WOFF + o;
        uint32_t b0 = packh(coeff * __ldg(&wb[(m0)     * MUL]),
                            coeff * __ldg(&wb[(m0 + 1) * MUL]));
        uint32_t b1 = packh(coeff * __ldg(&wb[(m0 + 8) * MUL]),
                            coeff * __ldg(&wb[(m0 + 9) * MUL]));
        dst[base + fr * 32 + lane] = make_uint2(b0, b1);
    }
}

// ---------------- main: fp16 2-term mma per 32-row tile ----------------
// GEMM per tile: M' = 32*DIM, N = K = MUL.  A[(r*DIM+i)][m] = x[r][m][i]
// split hi/lo fp16; B fp16 (coeff folded), fragments from global.
template <int MUL, int DIM, int IOFF2>
__device__ __forceinline__ void run_irrep(const float* __restrict__ x,
                                          float* __restrict__ y,
                                          int tile, char* smraw) {
    constexpr int K   = MUL;
    constexpr int CH  = MUL * DIM;
    constexpr int LD  = 2 * K + 8;         // A row stride (fp16)
    constexpr int WM  = DIM;
    constexpr int NBW = MUL / 32;
    constexpr int KS  = MUL / 16;
    constexpr int LDC = MUL + 2;           // C smem row stride (floats)

    __half* As = reinterpret_cast<__half*>(smraw);
    float*  Cs = reinterpret_cast<float*>(smraw);

    const int2 tt  = d_tiles[tile];
    const int row0 = tt.x;
    const int g    = tt.y;
    int nrows = d_starts[g + 1] - row0;
    if (nrows > TILE_R) nrows = TILE_R;

    const unsigned sbase = smem_u32(smraw);
    const int tid = threadIdx.x;

    // ---- stage A: x -> fp16 hi/lo planes, row-major [rowp][k] ----
    const float* xt = x + (size_t)row0 * CH;
    constexpr int IPR = K / 8;
    for (int e = tid; e < TILE_R * IPR; e += TPB) {
        const int r  = e / IPR;
        const int m0 = (e - r * IPR) * 8;
        float f[8 * DIM];
        if (r < nrows) {
            const float4* s = reinterpret_cast<const float4*>(xt + (size_t)r * CH + m0 * DIM);
            #pragma unroll
            for (int q = 0; q < 2 * DIM; q++) {
                float4 v = s[q];
                f[4*q] = v.x; f[4*q+1] = v.y; f[4*q+2] = v.z; f[4*q+3] = v.w;
            }
        } else {
            #pragma unroll
            for (int q = 0; q < 8 * DIM; q++) f[q] = 0.f;
        }
        #pragma unroll
        for (int i = 0; i < DIM; i++) {
            uint32_t hi[4], lo[4];
            #pragma unroll
            for (int q = 0; q < 4; q++) {
                float a = f[(2*q)   * DIM + i];
                float b = f[(2*q+1) * DIM + i];
                __half ha = __float2half(a);
                __half hb = __float2half(b);
                hi[q] = packh(__half2float(ha), __half2float(hb));
                lo[q] = packh(a - __half2float(ha), b - __half2float(hb));
            }
            const unsigned ab = sbase + (unsigned)((r * DIM + i) * LD + m0) * 2u;
            sts128(ab,          hi[0], hi[1], hi[2], hi[3]);
            sts128(ab + 2u * K, lo[0], lo[1], lo[2], lo[3]);
        }
    }
    __syncthreads();

    const int l  = tid & 31;
    const int wp = tid >> 5;
    const int wm = wp & 1;                 // 2 groups along M'
    const int nh = wp >> 1;                // 4 groups along N

    const unsigned a_lane = ((l & 15) * LD + ((l >> 4) << 3)) * 2u;
    const uint2* wfrag = d_wf + (size_t)g * SEG_U2 + IOFF2
                       + (size_t)(nh * NBW) * KS * 32 + l;

    float acc[WM][NBW][4];
    #pragma unroll
    for (int mt = 0; mt < WM; mt++)
        #pragma unroll
        for (int nb = 0; nb < NBW; nb++)
            #pragma unroll
            for (int q = 0; q < 4; q++) acc[mt][nb][q] = 0.f;

    for (int ks = 0; ks < KS; ks++) {
        uint2 bf[NBW];
        #pragma unroll
        for (int nb = 0; nb < NBW; nb++)
            bf[nb] = __ldg(&wfrag[(nb * KS + ks) * 32]);
        #pragma unroll
        for (int mt = 0; mt < WM; mt++) {
            const unsigned ab = sbase
                + (unsigned)(((wm * DIM + mt) * 16) * LD) * 2u
                + (unsigned)ks * 32u + a_lane;
            uint32_t ah[4], al[4];
            ldsm4(ah, ab);                 // x hi plane
            ldsm4(al, ab + 2u * K);        // x lo plane
            #pragma unroll
            for (int nb = 0; nb < NBW; nb++) {
                mma_f16(acc[mt][nb], ah, bf[nb].x, bf[nb].y);
                mma_f16(acc[mt][nb], al, bf[nb].x, bf[nb].y);
            }
        }
    }

    // ---- epilogue ----
    if (DIM == 1) {
        // direct: already row-coalesced float2 stores
        float* yt = y + (size_t)row0 * CH;
        #pragma unroll
        for (int mt = 0; mt < WM; mt++) {
            const int mrow0 = (wm * DIM + mt) * 16 + (l >> 2);
            #pragma unroll
            for (int nb = 0; nb < NBW; nb++) {
                const int n0 = nh * (MUL / 4) + nb * 8 + (l & 3) * 2;
                #pragma unroll
                for (int rr = 0; rr < 2; rr++) {
                    const int r = mrow0 + rr * 8;
                    if (r < nrows)
                        *reinterpret_cast<float2*>(&yt[(size_t)r * CH + n0]) =
                            make_float2(acc[mt][nb][rr * 2], acc[mt][nb][rr * 2 + 1]);
                }
            }
        }
    } else {
        // bounce through smem (reusing A region), then coalesced float4 stores
        __syncthreads();                    // all ldsm reads of As complete
        #pragma unroll
        for (int mt = 0; mt < WM; mt++) {
            const int mrow0 = (wm * DIM + mt) * 16 + (l >> 2);
            #pragma unroll
            for (int nb = 0; nb < NBW; nb++) {
                const int n0 = nh * (MUL / 4) + nb * 8 + (l & 3) * 2;
                #pragma unroll
                for (int rr = 0; rr < 2; rr++) {
                    *reinterpret_cast<float2*>(&Cs[(mrow0 + rr * 8) * LDC + n0]) =
                        make_float2(acc[mt][nb][rr * 2], acc[mt][nb][rr * 2 + 1]);
                }
            }
        }
        __syncthreads();
        float* yt = y + (size_t)row0 * CH;
        constexpr int CH4 = CH / 4;
        for (int e = tid; e < TILE_R * CH4; e += TPB) {
            const int r  = e / CH4;
            const int c0 = (e - r * CH4) * 4;
            if (r < nrows) {
                float v[4];
                #pragma unroll
                for (int j = 0; j < 4; j++) {
                    const int c = c0 + j;
                    const int o = c / DIM;
                    const int i = c - o * DIM;
                    v[j] = Cs[(r * DIM + i) * LDC + o];
                }
                *reinterpret_cast<float4*>(&yt[(size_t)r * CH + c0]) =
                    make_float4(v[0], v[1], v[2], v[3]);
            }
        }
    }
}

// smem union: A halfs irrep1 = 96*136*2 = 26112 B (max);
// C floats irrep1 = 96*66*4 = 25344 B <= 26112 ✓ ; irrep2: 21760 ✓
#define SMEM_BYTES 26112

__global__ __launch_bounds__(TPB, 4)
void lin_main(const float* __restrict__ x0, const float* __restrict__ x1,
              const float* __restrict__ x2, float* __restrict__ out) {
    __shared__ __align__(16) char smraw[SMEM_BYTES];
    const int b    = blockIdx.x;
    const int irr  = b % 3;                // interleave heavy/light tiles
    const int tile = b / 3;
    if (tile >= d_ntiles) return;
    if (irr == 0) {
        run_irrep<128, 1, 0>(x0, out, tile, smraw);
    } else if (irr == 1) {
        run_irrep<64, 3, 4096>(x1, out + (size_t)NELEM * 128, tile, smraw);
    } else {
        run_irrep<32, 5, 5120>(x2, out + (size_t)NELEM * (128 + 192), tile, smraw);
    }
}

extern "C" void kernel_launch(void* const* d_in, const int* in_sizes, int n_in,
                              void* d_out, int out_size) {
    const float* x0     = (const float*)d_in[0];
    const float* x1     = (const float*)d_in[1];
    const float* x2     = (const float*)d_in[2];
    const float* w      = (const float*)d_in[3];
    const int*   counts = (const int*)d_in[4];
    float*       out    = (float*)d_out;

    pre_kernel<<<4 * NSEG + 1, 256>>>(counts, w);
    lin_main<<<3 * MAX_TILES, TPB>>>(x0, x1, x2, out);
}

// round 16
// speedup vs baseline: 1.9233x; 1.0917x over previous
#include <cuda_runtime.h>
#include <cuda_fp16.h>
#include <cstdint>

#define W_DIM   21504
#define NSEG    64
#define NELEM   8192
#define TILE_R  32
#define MAX_TILES 320
#define TPB     256
#define SEG_U2  5376        // uint2 fp16 fragments per segment
#define PRE_Q   1344        // items per pre-block (SEG_U2/4)

// ---------------- device globals ----------------
__device__ int  d_starts[NSEG + 1];
__device__ int2 d_tiles[MAX_TILES];
__device__ int  d_ntiles;
__device__ __align__(16) uint2 d_wf[NSEG * SEG_U2];  // mma-fragment-ordered fp16 weights

// ---------------- wrappers ----------------
__device__ __forceinline__ void ldsm4(uint32_t* r, unsigned addr) {
    asm volatile("ldmatrix.sync.aligned.m8n8.x4.shared.b16 {%0,%1,%2,%3}, [%4];"
                 : "=r"(r[0]), "=r"(r[1]), "=r"(r[2]), "=r"(r[3]) : "r"(addr));
}
__device__ __forceinline__ void mma_f16(float* c, const uint32_t* a,
                                        uint32_t b0, uint32_t b1) {
    asm volatile("mma.sync.aligned.m16n8k16.row.col.f32.f16.f16.f32 "
                 "{%0,%1,%2,%3}, {%4,%5,%6,%7}, {%8,%9}, {%0,%1,%2,%3};"
                 : "+f"(c[0]), "+f"(c[1]), "+f"(c[2]), "+f"(c[3])
                 : "r"(a[0]), "r"(a[1]), "r"(a[2]), "r"(a[3]), "r"(b0), "r"(b1));
}
__device__ __forceinline__ uint32_t packh(float a, float b) {
    __half2 h = __floats2half2_rn(a, b);    // .x = a = low half (even k)
    return *reinterpret_cast<uint32_t*>(&h);
}
__device__ __forceinline__ void sts128(unsigned a, uint32_t x, uint32_t y,
                                       uint32_t z, uint32_t w) {
    asm volatile("st.shared.v4.b32 [%0], {%1,%2,%3,%4};"
                 :: "r"(a), "r"(x), "r"(y), "r"(z), "r"(w));
}
__device__ __forceinline__ unsigned smem_u32(const void* p) {
    unsigned a;
    asm("{ .reg .u64 t; cvta.to.shared.u64 t, %1; cvt.u32.u64 %0, t; }"
        : "=r"(a) : "l"(p));
    return a;
}

// ---------------- prekernel: direct-gather fp16 fragments + scan ------------
__global__ void pre_kernel(const int* __restrict__ counts,
                           const float* __restrict__ w) {
    if (blockIdx.x == 4 * NSEG) {
        __shared__ int wsum[2], wtsum[2];
        const int t = threadIdx.x;
        int c = 0, nt = 0, sc = 0, st = 0;
        if (t < 64) {
            c  = counts[t];
            nt = (c + TILE_R - 1) >> 5;
            sc = c; st = nt;
            #pragma unroll
            for (int d = 1; d < 32; d <<= 1) {
                int a = __shfl_up_sync(0xffffffffu, sc, d);
                int b = __shfl_up_sync(0xffffffffu, st, d);
                if ((t & 31) >= d) { sc += a; st += b; }
            }
            if ((t & 31) == 31) { wsum[t >> 5] = sc; wtsum[t >> 5] = st; }
        }
        __syncthreads();
        if (t < 64) {
            if (t >= 32) { sc += wsum[0]; st += wtsum[0]; }
            const int startc = sc - c;
            const int startt = st - nt;
            d_starts[t] = startc;
            if (t == 63) { d_starts[NSEG] = sc; d_ntiles = st; }
            for (int k = 0; k < nt; k++)
                d_tiles[startt + k] = make_int2(startc + TILE_R * k, t);
        }
        return;
    }
    // Each w element feeds exactly one fragment -> direct gather, no staging.
    const int g = blockIdx.x >> 2;
    const int q = blockIdx.x & 3;
    const float* wg = w + (size_t)g * W_DIM;
    uint2* dst = d_wf + (size_t)g * SEG_U2;
    const int end = (q + 1) * PRE_Q;
    for (int it = q * PRE_Q + threadIdx.x; it < end; it += 256) {
        int MUL, KS, WOFF, base; float coeff; int rem;
        if (it < 4096)      { MUL=128; KS=8; WOFF=0;     base=0;    coeff=0.011048543456039806f; rem=it; }
        else if (it < 5120) { MUL=64;  KS=4; WOFF=16384; base=4096; coeff=0.015625f;             rem=it-4096; }
        else                { MUL=32;  KS=2; WOFF=20480; base=5120; coeff=0.022097086912079613f; rem=it-5120; }
        const int lane = rem & 31;
        const int fr   = rem >> 5;
        const int ks   = fr % KS;
        const int nbl  = fr / KS;
        const int o    = nbl * 8 + (lane >> 2);
        const int m0   = ks * 16 + (lane & 3) * 2;
        const float* wb = wg + WOFF + o;
        uint32_t b0 = packh(coeff * __ldg(&wb[(m0)     * MUL]),
                            coeff * __ldg(&wb[(m0 + 1) * MUL]));
        uint32_t b1 = packh(coeff * __ldg(&wb[(m0 + 8) * MUL]),
                            coeff * __ldg(&wb[(m0 + 9) * MUL]));
        dst[base + fr * 32 + lane] = make_uint2(b0, b1);
    }
}

// ---------------- main: single-fp16 mma per 32-row tile ----------------
// GEMM per tile: M' = 32*DIM, N = K = MUL.  A[(r*DIM+i)][m] = fp16(x[r][m][i])
// B fp16 (coeff folded), fragments from global.
template <int MUL, int DIM, int IOFF2>
__device__ __forceinline__ void run_irrep(const float* __restrict__ x,
                                          float* __restrict__ y,
                                          int tile, char* smraw) {
    constexpr int K   = MUL;
    constexpr int CH  = MUL * DIM;
    constexpr int LD  = K + 8;             // A row stride (fp16), single plane
    constexpr int WM  = DIM;
    constexpr int NBW = MUL / 32;
    constexpr int KS  = MUL / 16;
    constexpr int LDC = MUL + 2;           // C smem row stride (floats)

    float* Cs = reinterpret_cast<float*>(smraw);

    const int2 tt  = d_tiles[tile];
    const int row0 = tt.x;
    const int g    = tt.y;
    int nrows = d_starts[g + 1] - row0;
    if (nrows > TILE_R) nrows = TILE_R;

    const unsigned sbase = smem_u32(smraw);
    const int tid = threadIdx.x;

    // ---- stage A: x -> fp16, row-major [rowp][k] ----
    const float* xt = x + (size_t)row0 * CH;
    constexpr int IPR = K / 8;
    for (int e = tid; e < TILE_R * IPR; e += TPB) {
        const int r  = e / IPR;
        const int m0 = (e - r * IPR) * 8;
        float f[8 * DIM];
        if (r < nrows) {
            const float4* s = reinterpret_cast<const float4*>(xt + (size_t)r * CH + m0 * DIM);
            #pragma unroll
            for (int q = 0; q < 2 * DIM; q++) {
                float4 v = s[q];
                f[4*q] = v.x; f[4*q+1] = v.y; f[4*q+2] = v.z; f[4*q+3] = v.w;
            }
        } else {
            #pragma unroll
            for (int q = 0; q < 8 * DIM; q++) f[q] = 0.f;
        }
        #pragma unroll
        for (int i = 0; i < DIM; i++) {
            uint32_t hv[4];
            #pragma unroll
            for (int q = 0; q < 4; q++)
                hv[q] = packh(f[(2*q) * DIM + i], f[(2*q+1) * DIM + i]);
            const unsigned ab = sbase + (unsigned)((r * DIM + i) * LD + m0) * 2u;
            sts128(ab, hv[0], hv[1], hv[2], hv[3]);
        }
    }
    __syncthreads();

    const int l  = tid & 31;
    const int wp = tid >> 5;
    const int wm = wp & 1;                 // 2 groups along M'
    const int nh = wp >> 1;                // 4 groups along N

    const unsigned a_lane = ((l & 15) * LD + ((l >> 4) << 3)) * 2u;
    const uint2* wfrag = d_wf + (size_t)g * SEG_U2 + IOFF2
                       + (size_t)(nh * NBW) * KS * 32 + l;

    float acc[WM][NBW][4];
    #pragma unroll
    for (int mt = 0; mt < WM; mt++)
        #pragma unroll
        for (int nb = 0; nb < NBW; nb++)
            #pragma unroll
            for (int q = 0; q < 4; q++) acc[mt][nb][q] = 0.f;

    for (int ks = 0; ks < KS; ks++) {
        uint2 bf[NBW];
        #pragma unroll
        for (int nb = 0; nb < NBW; nb++)
            bf[nb] = __ldg(&wfrag[(nb * KS + ks) * 32]);
        #pragma unroll
        for (int mt = 0; mt < WM; mt++) {
            const unsigned ab = sbase
                + (unsigned)(((wm * DIM + mt) * 16) * LD) * 2u
                + (unsigned)ks * 32u + a_lane;
            uint32_t ah[4];
            ldsm4(ah, ab);
            #pragma unroll
            for (int nb = 0; nb < NBW; nb++)
                mma_f16(acc[mt][nb], ah, bf[nb].x, bf[nb].y);
        }
    }

    // ---- epilogue ----
    if (DIM == 1) {
        float* yt = y + (size_t)row0 * CH;
        #pragma unroll
        for (int mt = 0; mt < WM; mt++) {
            const int mrow0 = (wm * DIM + mt) * 16 + (l >> 2);
            #pragma unroll
            for (int nb = 0; nb < NBW; nb++) {
                const int n0 = nh * (MUL / 4) + nb * 8 + (l & 3) * 2;
                #pragma unroll
                for (int rr = 0; rr < 2; rr++) {
                    const int r = mrow0 + rr * 8;
                    if (r < nrows)
                        *reinterpret_cast<float2*>(&yt[(size_t)r * CH + n0]) =
                            make_float2(acc[mt][nb][rr * 2], acc[mt][nb][rr * 2 + 1]);
                }
            }
        }
    } else {
        // bounce through smem (reusing A region), then coalesced float4 stores
        __syncthreads();                    // all ldsm reads complete
        #pragma unroll
        for (int mt = 0; mt < WM; mt++) {
            const int mrow0 = (wm * DIM + mt) * 16 + (l >> 2);
            #pragma unroll
            for (int nb = 0; nb < NBW; nb++) {
                const int n0 = nh * (MUL / 4) + nb * 8 + (l & 3) * 2;
                #pragma unroll
                for (int rr = 0; rr < 2; rr++) {
                    *reinterpret_cast<float2*>(&Cs[(mrow0 + rr * 8) * LDC + n0]) =
                        make_float2(acc[mt][nb][rr * 2], acc[mt][nb][rr * 2 + 1]);
                }
            }
        }
        __syncthreads();
        float* yt = y + (size_t)row0 * CH;
        constexpr int CH4 = CH / 4;
        for (int e = tid; e < TILE_R * CH4; e += TPB) {
            const int r  = e / CH4;
            const int c0 = (e - r * CH4) * 4;
            if (r < nrows) {
                float v[4];
                #pragma unroll
                for (int j = 0; j < 4; j++) {
                    const int c = c0 + j;
                    const int o = c / DIM;
                    const int i = c - o * DIM;
                    v[j] = Cs[(r * DIM + i) * LDC + o];
                }
                *reinterpret_cast<float4*>(&yt[(size_t)r * CH + c0]) =
                    make_float4(v[0], v[1], v[2], v[3]);
            }
        }
    }
}

// smem: max over {A halfs, C floats}:
//   A: irrep0 32*136*2=8704; irrep1 96*72*2=13824; irrep2 160*40*2=12800
//   C: irrep1 96*66*4=25344 (max); irrep2 160*34*4=21760
#define SMEM_BYTES 25600

__global__ __launch_bounds__(TPB, 4)
void lin_main(const float* __restrict__ x0, const float* __restrict__ x1,
              const float* __restrict__ x2, float* __restrict__ out) {
    __shared__ __align__(16) char smraw[SMEM_BYTES];
    const int b    = blockIdx.x;
    const int irr  = b % 3;                // interleave heavy/light tiles
    const int tile = b / 3;
    if (tile >= d_ntiles) return;
    if (irr == 0) {
        run_irrep<128, 1, 0>(x0, out, tile, smraw);
    } else if (irr == 1) {
        run_irrep<64, 3, 4096>(x1, out + (size_t)NELEM * 128, tile, smraw);
    } else {
        run_irrep<32, 5, 5120>(x2, out + (size_t)NELEM * (128 + 192), tile, smraw);
    }
}

extern "C" void kernel_launch(void* const* d_in, const int* in_sizes, int n_in,
                              void* d_out, int out_size) {
    const float* x0     = (const float*)d_in[0];
    const float* x1     = (const float*)d_in[1];
    const float* x2     = (const float*)d_in[2];
    const float* w      = (const float*)d_in[3];
    const int*   counts = (const int*)d_in[4];
    float*       out    = (float*)d_out;

    pre_kernel<<<4 * NSEG + 1, 256>>>(counts, w);
    lin_main<<<3 * MAX_TILES, TPB>>>(x0, x1, x2, out);
}